// round 14
// baseline (speedup 1.0000x reference)
#include <cuda_runtime.h>
#include <math.h>

// Problem constants
#define Bc   32
#define Nc   4096
#define Dc   128
#define Kc   512
#define NPBc 2048
#define Mc   (Bc * NPBc)   // 65536
#define Ec   (Bc * Nc)     // 131072
#define TDc  384
#define MAXC 32
#define BKc  (Bc * Kc)     // 16384

// Output layout (flattened tuple, fp32)
#define EMD_OFF 32768
#define HID_OFF 2129920

typedef unsigned long long ull;

// ---------------- scratch (static device globals; no allocations) -------------
__device__ __align__(16) float  g_v[Bc * TDc];
__device__ float                g_sf[Bc];
__device__ float                g_att[Ec];
__device__ int                  g_cnt[Mc];
__device__ int                  g_list[Mc * MAXC];
__device__ double               g_agg[Mc];
__device__ int                  g_topk[BKc];
__device__ __align__(16) float  g_emd[(size_t)BKc * Dc];

// ================= K1: fused zero + per-batch precompute (coalesced, ILP) =======
__global__ void __launch_bounds__(256) k_init(
    const float* __restrict__ qh, const float* __restrict__ qr,
    const float* __restrict__ qt, const float* __restrict__ Wq,
    const float* __restrict__ bq, const float* __restrict__ Wa,
    const float* __restrict__ ba, const float* __restrict__ Watt,
    const float* __restrict__ batt) {
    cudaTriggerProgrammaticLaunchCompletion();
    if (blockIdx.x < 256) {
        int i = blockIdx.x * 256 + threadIdx.x;
        g_cnt[i] = 0;
        g_agg[i] = 0.0;
        return;
    }
    int b    = blockIdx.x - 256;
    int tid  = threadIdx.x;
    int t    = tid & 127;
    int half = tid >> 7;
    int lane = tid & 31;
    int warp = tid >> 5;
    __shared__ float xS[TDc];
    __shared__ float redq[2 * Dc];
    __shared__ __align__(16) float cS[Dc];
    __shared__ float red[Dc];

    if (tid < 128) { xS[tid] = qh[b * Dc + tid]; xS[256 + tid] = qt[b * Dc + tid]; }
    else           { xS[tid] = qr[b * Dc + (tid - 128)]; }
    __syncthreads();

    {
        int jb = half * 192;
        float a0 = 0.f, a1 = 0.f, a2 = 0.f, a3 = 0.f;
#pragma unroll 8
        for (int j = 0; j < 192; j += 4) {
            a0 = fmaf(xS[jb + j],     Wq[(size_t)(jb + j) * Dc + t],     a0);
            a1 = fmaf(xS[jb + j + 1], Wq[(size_t)(jb + j + 1) * Dc + t], a1);
            a2 = fmaf(xS[jb + j + 2], Wq[(size_t)(jb + j + 2) * Dc + t], a2);
            a3 = fmaf(xS[jb + j + 3], Wq[(size_t)(jb + j + 3) * Dc + t], a3);
        }
        redq[half * Dc + t] = (a0 + a1) + (a2 + a3);
    }
    __syncthreads();

    if (tid < 128) {
        float q  = bq[t] + redq[t] + redq[Dc + t];
        float w1 = Watt[t], w2 = Watt[Dc + t], w3 = Watt[2 * Dc + t];
        float c  = q * w1 - w2 + w3;
        cS[t]  = c;
        red[t] = q * (w2 + w3) + ba[t] * c;
    }
    __syncthreads();
    for (int off = 64; off > 0; off >>= 1) {
        if (tid < off) red[tid] += red[tid + off];
        __syncthreads();
    }
    if (tid == 0) g_sf[b] = red[0] + batt[0];

    float4 cl = ((const float4*)cS)[lane];
    int base = warp * 48;
    for (int jj = 0; jj < 48; jj += 4) {
        int j = base + jj;
        float4 w0 = ((const float4*)(Wa + (size_t)(j)     * Dc))[lane];
        float4 w1 = ((const float4*)(Wa + (size_t)(j + 1) * Dc))[lane];
        float4 w2 = ((const float4*)(Wa + (size_t)(j + 2) * Dc))[lane];
        float4 w3 = ((const float4*)(Wa + (size_t)(j + 3) * Dc))[lane];
        float d0 = w0.x * cl.x; d0 = fmaf(w0.y, cl.y, d0);
        d0 = fmaf(w0.z, cl.z, d0); d0 = fmaf(w0.w, cl.w, d0);
        float d1 = w1.x * cl.x; d1 = fmaf(w1.y, cl.y, d1);
        d1 = fmaf(w1.z, cl.z, d1); d1 = fmaf(w1.w, cl.w, d1);
        float d2 = w2.x * cl.x; d2 = fmaf(w2.y, cl.y, d2);
        d2 = fmaf(w2.z, cl.z, d2); d2 = fmaf(w2.w, cl.w, d2);
        float d3 = w3.x * cl.x; d3 = fmaf(w3.y, cl.y, d3);
        d3 = fmaf(w3.z, cl.z, d3); d3 = fmaf(w3.w, cl.w, d3);
#pragma unroll
        for (int off = 16; off > 0; off >>= 1) {
            d0 += __shfl_xor_sync(0xffffffffu, d0, off);
            d1 += __shfl_xor_sync(0xffffffffu, d1, off);
            d2 += __shfl_xor_sync(0xffffffffu, d2, off);
            d3 += __shfl_xor_sync(0xffffffffu, d3, off);
        }
        if (lane == 0) {
            g_v[b * TDc + j]     = d0;
            g_v[b * TDc + j + 1] = d1;
            g_v[b * TDc + j + 2] = d2;
            g_v[b * TDc + j + 3] = d3;
        }
    }
}

// ================= K2: per-edge att (2 edges/warp), PDL-overlapped ===============
__global__ void __launch_bounds__(256) k_edge(
    const float* __restrict__ rn,  const float* __restrict__ tn,
    const float* __restrict__ tin, const float* __restrict__ hidden,
    const float* __restrict__ Wrule, const float* __restrict__ brule,
    const int* __restrict__ tail_index) {
    cudaTriggerProgrammaticLaunchCompletion();
    int w    = blockIdx.x * 8 + (threadIdx.x >> 5);
    int lane = threadIdx.x & 31;
    int e0   = w * 2, e1 = e0 + 1;
    int b    = e0 >> 12;

    const float4 r4a  = ((const float4*)(rn  + (size_t)e0 * Dc))[lane];
    const float4 r4b  = ((const float4*)(rn  + (size_t)e1 * Dc))[lane];
    const float4 t4a  = __ldcs((const float4*)(tn  + (size_t)e0 * Dc) + lane);
    const float4 t4b  = __ldcs((const float4*)(tn  + (size_t)e1 * Dc) + lane);
    const float4 ti4a = ((const float4*)(tin + (size_t)e0 * Dc))[lane];
    const float4 ti4b = ((const float4*)(tin + (size_t)e1 * Dc))[lane];
    const float4 h4a  = ((const float4*)(hidden + (size_t)e0 * Dc))[lane];
    const float4 h4b  = ((const float4*)(hidden + (size_t)e1 * Dc))[lane];
    float4 w4 = ((const float4*)Wrule)[lane];
    int   m0 = tail_index[e0];
    int   m1 = tail_index[e1];
    float br = brule[0];

    cudaGridDependencySynchronize();

    const float4* vp = (const float4*)(g_v + b * TDc);
    float4 vA = vp[lane], vB = vp[32 + lane], vC = vp[64 + lane];

    float s1a = r4a.x * vA.x;
    s1a = fmaf(r4a.y, vA.y, s1a);  s1a = fmaf(r4a.z, vA.z, s1a);  s1a = fmaf(r4a.w, vA.w, s1a);
    s1a = fmaf(t4a.x, vB.x, s1a);  s1a = fmaf(t4a.y, vB.y, s1a);
    s1a = fmaf(t4a.z, vB.z, s1a);  s1a = fmaf(t4a.w, vB.w, s1a);
    s1a = fmaf(ti4a.x, vC.x, s1a); s1a = fmaf(ti4a.y, vC.y, s1a);
    s1a = fmaf(ti4a.z, vC.z, s1a); s1a = fmaf(ti4a.w, vC.w, s1a);

    float s1b = r4b.x * vA.x;
    s1b = fmaf(r4b.y, vA.y, s1b);  s1b = fmaf(r4b.z, vA.z, s1b);  s1b = fmaf(r4b.w, vA.w, s1b);
    s1b = fmaf(t4b.x, vB.x, s1b);  s1b = fmaf(t4b.y, vB.y, s1b);
    s1b = fmaf(t4b.z, vB.z, s1b);  s1b = fmaf(t4b.w, vB.w, s1b);
    s1b = fmaf(ti4b.x, vC.x, s1b); s1b = fmaf(ti4b.y, vC.y, s1b);
    s1b = fmaf(ti4b.z, vC.z, s1b); s1b = fmaf(ti4b.w, vC.w, s1b);

    float s2a = h4a.x * w4.x;
    s2a = fmaf(h4a.y, w4.y, s2a);  s2a = fmaf(h4a.z, w4.z, s2a);  s2a = fmaf(h4a.w, w4.w, s2a);
    float s2b = h4b.x * w4.x;
    s2b = fmaf(h4b.y, w4.y, s2b);  s2b = fmaf(h4b.z, w4.z, s2b);  s2b = fmaf(h4b.w, w4.w, s2b);

#pragma unroll
    for (int off = 16; off > 0; off >>= 1) {
        s1a += __shfl_xor_sync(0xffffffffu, s1a, off);
        s1b += __shfl_xor_sync(0xffffffffu, s1b, off);
        s2a += __shfl_xor_sync(0xffffffffu, s2a, off);
        s2b += __shfl_xor_sync(0xffffffffu, s2b, off);
    }

    float sf = g_sf[b];
    if (lane == 0) {
        float att = 0.5f * (1.0f / (1.0f + expf(-(s1a + sf))) +
                            1.0f / (1.0f + expf(-(s2a + br))));
        g_att[e0] = att;
        atomicAdd(&g_agg[m0], (double)att);
        int pos = atomicAdd(&g_cnt[m0], 1);
        if (pos < MAXC) g_list[m0 * MAXC + pos] = e0;
    } else if (lane == 16) {
        float att = 0.5f * (1.0f / (1.0f + expf(-(s1b + sf))) +
                            1.0f / (1.0f + expf(-(s2b + br))));
        g_att[e1] = att;
        atomicAdd(&g_agg[m1], (double)att);
        int pos = atomicAdd(&g_cnt[m1], 1);
        if (pos < MAXC) g_list[m1 * MAXC + pos] = e1;
    }
}

// ================= K3: radix-select top-512, 256 threads (low barrier cost) ======
__global__ void __launch_bounds__(256) k_topk(const int* __restrict__ tnodes,
                                              float* __restrict__ out) {
    cudaTriggerProgrammaticLaunchCompletion();   // let k_gather pre-place
    int b    = blockIdx.x;
    int tid  = threadIdx.x;
    int lane = tid & 31;
    int warp = tid >> 5;

    __shared__ unsigned int hist[256];
    __shared__ unsigned int sufS[258];
    __shared__ ull sPrefix;
    __shared__ int sRem;
    __shared__ int sCnt;
    __shared__ ull arr[Kc];

    cudaGridDependencySynchronize();   // wait for k_edge's g_agg

    ull kk[8];
#pragma unroll
    for (int j = 0; j < 8; ++j) {
        int i = tid + 256 * j;
        kk[j] = (__double_as_longlong(g_agg[b * NPBc + i]) & 0xFFFFFFFFFFFF0000ull)
                | (ull)(2047 - i);
    }
    ull prefix = 0;
    int rem    = Kc;
    for (int d = 7; d >= 0; --d) {
        hist[tid] = 0;
        __syncthreads();
        int shHi = (d < 7) ? (8 * d + 8) : 0;
#pragma unroll
        for (int j = 0; j < 8; ++j) {
            bool mm = (d == 7) || ((kk[j] >> shHi) == prefix);
            if (mm) atomicAdd(&hist[(unsigned)(kk[j] >> (8 * d)) & 0xFF], 1u);
        }
        __syncthreads();
        if (tid < 32) {
            unsigned v[8], suf[8];
            unsigned run = 0;
#pragma unroll
            for (int j = 7; j >= 0; --j) { v[j] = hist[lane * 8 + j]; run += v[j]; suf[j] = run; }
            unsigned tot = run, s = tot;
#pragma unroll
            for (int off = 1; off < 32; off <<= 1) {
                unsigned o = __shfl_down_sync(0xffffffffu, s, off);
                if (lane + off < 32) s += o;
            }
            unsigned excl = s - tot;
#pragma unroll
            for (int j = 0; j < 8; ++j) sufS[lane * 8 + j] = suf[j] + excl;
            if (lane == 0) sufS[256] = 0;
            __syncwarp();
#pragma unroll
            for (int j = 0; j < 8; ++j) {
                int t = lane * 8 + j;
                unsigned st = sufS[t], st1 = sufS[t + 1];
                if (st >= (unsigned)rem && st1 < (unsigned)rem) {
                    sPrefix = (prefix << 8) | (ull)(unsigned)t;
                    sRem    = rem - (int)st1;
                }
            }
        }
        __syncthreads();
        prefix = sPrefix;
        rem    = sRem;
        __syncthreads();
    }
    ull T = prefix;

    if (tid == 0) sCnt = 0;
    __syncthreads();
#pragma unroll
    for (int j = 0; j < 8; ++j)
        if (kk[j] >= T) arr[atomicAdd(&sCnt, 1)] = kk[j];
    __syncthreads();

    // bitonic sort 512 descending, 256 threads (2 elements each)
    for (int g = warp; g < 16; g += 8) {
        int idx = g * 32 + lane;
        ull v = arr[idx];
#pragma unroll
        for (int size = 2; size <= 32; size <<= 1)
#pragma unroll
            for (int stride = size >> 1; stride >= 1; stride >>= 1) {
                ull  vo  = __shfl_xor_sync(0xffffffffu, v, stride);
                bool low = (lane & stride) == 0;
                bool up  = ((idx & size) == 0);
                bool pm  = v > vo;
                if (pm != (up == low)) v = vo;
            }
        arr[idx] = v;
    }
    __syncthreads();
    for (int size = 64; size <= Kc; size <<= 1) {
        for (int stride = size >> 1; stride >= 32; stride >>= 1) {
            for (int t = tid; t < Kc; t += 256) {
                int l = t ^ stride;
                if (l > t) {
                    bool up = ((t & size) == 0);
                    ull v1 = arr[t], v2 = arr[l];
                    bool prec = v1 > v2;
                    if (up ? !prec : prec) { arr[t] = v2; arr[l] = v1; }
                }
            }
            __syncthreads();
        }
        for (int g = warp; g < 16; g += 8) {
            int idx = g * 32 + lane;
            ull v = arr[idx];
            bool up = ((idx & size) == 0);
#pragma unroll
            for (int stride = 16; stride >= 1; stride >>= 1) {
                ull  vo  = __shfl_xor_sync(0xffffffffu, v, stride);
                bool low = (lane & stride) == 0;
                bool pm  = v > vo;
                if (pm != (up == low)) v = vo;
            }
            arr[idx] = v;
        }
        __syncthreads();
    }

    for (int t = tid; t < Kc; t += 256) {
        int i = 2047 - (int)(arr[t] & 0xFFFFull);
        int m = b * NPBc + i;
        g_topk[b * Kc + t] = m;
        out[(size_t)(b * Kc + t) * 2 + 0] = (float)tnodes[m * 3 + 1];
        out[(size_t)(b * Kc + t) * 2 + 1] = (float)tnodes[m * 3 + 2];
    }
}

// ---- warp bitonic ascending sort of 32 unsigned (distinct; invalid=0xffffffff) --
__device__ __forceinline__ unsigned warp_sort_asc(unsigned v, int lane) {
#pragma unroll
    for (int size = 2; size <= 32; size <<= 1) {
#pragma unroll
        for (int stride = size >> 1; stride >= 1; stride >>= 1) {
            unsigned vo = __shfl_xor_sync(0xffffffffu, v, stride);
            bool low = (lane & stride) == 0;
            bool up  = ((lane & size) == 0);
            bool mineSmall = v < vo;
            if (mineSmall != (up == low)) v = vo;
        }
    }
    return v;
}

// ================= K4: gather — 1 row per warp-pair (R11 shape), PDL ============
__global__ void __launch_bounds__(256, 6) k_gather(
    const float* __restrict__ qh, const float* __restrict__ rn,
    const float* __restrict__ tin, const float* __restrict__ hidden,
    const float* __restrict__ temd, float* __restrict__ out) {
    cudaTriggerProgrammaticLaunchCompletion();   // let k_out pre-place + preload W
    int warp = threadIdx.x >> 5;
    int row  = blockIdx.x * 4 + (warp >> 1);
    int role = warp & 1;
    int lane = threadIdx.x & 31;
    int b    = row >> 9;

    float4 qh4 = ((const float4*)(qh + (size_t)b * Dc))[lane];  // pre-sync

    cudaGridDependencySynchronize();   // wait for k_topk's g_topk

    int m = g_topk[row];
    int k = g_cnt[m];
    if (k > MAXC) k = MAXC;
    unsigned ev = (lane < k) ? (unsigned)g_list[m * MAXC + lane] : 0xffffffffu;
    unsigned sorted = warp_sort_asc(ev, lane);
    float attL = (lane < k) ? g_att[(int)sorted] : 0.f;

    if (role == 0) {
        float aggf = (float)g_agg[m];
        float4 acc = ((const float4*)(temd + (size_t)m * Dc))[lane];
        acc.x = fmaf(aggf, qh4.x, acc.x);
        acc.y = fmaf(aggf, qh4.y, acc.y);
        acc.z = fmaf(aggf, qh4.z, acc.z);
        acc.w = fmaf(aggf, qh4.w, acc.w);

        int r = 0;
        for (; r + 3 < k; r += 4) {
            int e0 = (int)__shfl_sync(0xffffffffu, sorted, r);
            int e1 = (int)__shfl_sync(0xffffffffu, sorted, r + 1);
            int e2 = (int)__shfl_sync(0xffffffffu, sorted, r + 2);
            int e3 = (int)__shfl_sync(0xffffffffu, sorted, r + 3);
            float a0 = __shfl_sync(0xffffffffu, attL, r);
            float a1 = __shfl_sync(0xffffffffu, attL, r + 1);
            float a2 = __shfl_sync(0xffffffffu, attL, r + 2);
            float a3 = __shfl_sync(0xffffffffu, attL, r + 3);
            float4 r40  = ((const float4*)(rn  + (size_t)e0 * Dc))[lane];
            float4 ti40 = ((const float4*)(tin + (size_t)e0 * Dc))[lane];
            float4 r41  = ((const float4*)(rn  + (size_t)e1 * Dc))[lane];
            float4 ti41 = ((const float4*)(tin + (size_t)e1 * Dc))[lane];
            float4 r42  = ((const float4*)(rn  + (size_t)e2 * Dc))[lane];
            float4 ti42 = ((const float4*)(tin + (size_t)e2 * Dc))[lane];
            float4 r43  = ((const float4*)(rn  + (size_t)e3 * Dc))[lane];
            float4 ti43 = ((const float4*)(tin + (size_t)e3 * Dc))[lane];
            acc.x += a0 * (r40.x + ti40.x) + a1 * (r41.x + ti41.x);
            acc.y += a0 * (r40.y + ti40.y) + a1 * (r41.y + ti41.y);
            acc.z += a0 * (r40.z + ti40.z) + a1 * (r41.z + ti41.z);
            acc.w += a0 * (r40.w + ti40.w) + a1 * (r41.w + ti41.w);
            acc.x += a2 * (r42.x + ti42.x) + a3 * (r43.x + ti43.x);
            acc.y += a2 * (r42.y + ti42.y) + a3 * (r43.y + ti43.y);
            acc.z += a2 * (r42.z + ti42.z) + a3 * (r43.z + ti43.z);
            acc.w += a2 * (r42.w + ti42.w) + a3 * (r43.w + ti43.w);
        }
        if (r + 1 < k) {
            int e0 = (int)__shfl_sync(0xffffffffu, sorted, r);
            int e1 = (int)__shfl_sync(0xffffffffu, sorted, r + 1);
            float a0 = __shfl_sync(0xffffffffu, attL, r);
            float a1 = __shfl_sync(0xffffffffu, attL, r + 1);
            float4 r40  = ((const float4*)(rn  + (size_t)e0 * Dc))[lane];
            float4 ti40 = ((const float4*)(tin + (size_t)e0 * Dc))[lane];
            float4 r41  = ((const float4*)(rn  + (size_t)e1 * Dc))[lane];
            float4 ti41 = ((const float4*)(tin + (size_t)e1 * Dc))[lane];
            acc.x += a0 * (r40.x + ti40.x) + a1 * (r41.x + ti41.x);
            acc.y += a0 * (r40.y + ti40.y) + a1 * (r41.y + ti41.y);
            acc.z += a0 * (r40.z + ti40.z) + a1 * (r41.z + ti41.z);
            acc.w += a0 * (r40.w + ti40.w) + a1 * (r41.w + ti41.w);
            r += 2;
        }
        if (r < k) {
            int e = (int)__shfl_sync(0xffffffffu, sorted, r);
            float a = __shfl_sync(0xffffffffu, attL, r);
            float4 r4  = ((const float4*)(rn  + (size_t)e * Dc))[lane];
            float4 ti4 = ((const float4*)(tin + (size_t)e * Dc))[lane];
            acc.x += a * (r4.x + ti4.x);
            acc.y += a * (r4.y + ti4.y);
            acc.z += a * (r4.z + ti4.z);
            acc.w += a * (r4.w + ti4.w);
        }
        ((float4*)(g_emd + (size_t)row * Dc))[lane] = acc;
    } else {
        float4 hac = make_float4(0.f, 0.f, 0.f, 0.f);
        int r = 0;
        for (; r + 3 < k; r += 4) {
            int e0 = (int)__shfl_sync(0xffffffffu, sorted, r);
            int e1 = (int)__shfl_sync(0xffffffffu, sorted, r + 1);
            int e2 = (int)__shfl_sync(0xffffffffu, sorted, r + 2);
            int e3 = (int)__shfl_sync(0xffffffffu, sorted, r + 3);
            float4 h0 = ((const float4*)(hidden + (size_t)e0 * Dc))[lane];
            float4 h1 = ((const float4*)(hidden + (size_t)e1 * Dc))[lane];
            float4 h2 = ((const float4*)(hidden + (size_t)e2 * Dc))[lane];
            float4 h3 = ((const float4*)(hidden + (size_t)e3 * Dc))[lane];
            hac.x += h0.x + h1.x; hac.y += h0.y + h1.y;
            hac.z += h0.z + h1.z; hac.w += h0.w + h1.w;
            hac.x += h2.x + h3.x; hac.y += h2.y + h3.y;
            hac.z += h2.z + h3.z; hac.w += h2.w + h3.w;
        }
        if (r + 1 < k) {
            int e0 = (int)__shfl_sync(0xffffffffu, sorted, r);
            int e1 = (int)__shfl_sync(0xffffffffu, sorted, r + 1);
            float4 h0 = ((const float4*)(hidden + (size_t)e0 * Dc))[lane];
            float4 h1 = ((const float4*)(hidden + (size_t)e1 * Dc))[lane];
            hac.x += h0.x + h1.x; hac.y += h0.y + h1.y;
            hac.z += h0.z + h1.z; hac.w += h0.w + h1.w;
            r += 2;
        }
        if (r < k) {
            int e = (int)__shfl_sync(0xffffffffu, sorted, r);
            float4 h0 = ((const float4*)(hidden + (size_t)e * Dc))[lane];
            hac.x += h0.x; hac.y += h0.y; hac.z += h0.z; hac.w += h0.w;
        }
        ((float4*)(out + HID_OFF + (size_t)row * Dc))[lane] = hac;
    }
}

// ================= K5: output matvec; W half0 preloaded pre-sync (PDL) ===========
__global__ void __launch_bounds__(256) k_out(const float* __restrict__ Wout,
                                             const float* __restrict__ bout,
                                             float* __restrict__ out) {
    __shared__ float Wsh[64 * Dc];   // 32KB: one half of W_out
    __shared__ float Ash[32 * Dc];   // 16KB: this block's 32 emd rows
    int tid  = threadIdx.x;
    int tcol = tid & 31;
    int trow = tid >> 5;
    int rowbase = blockIdx.x * 32;

    for (int i = tid; i < 2048; i += 256)
        ((float4*)Wsh)[i] = ((const float4*)Wout)[i];
    float4 b4 = ((const float4*)bout)[tcol];

    cudaGridDependencySynchronize();   // wait for k_gather's g_emd

    for (int i = tid; i < 1024; i += 256)
        ((float4*)Ash)[i] = ((const float4*)(g_emd + (size_t)rowbase * Dc))[i];
    __syncthreads();

    float4 a0 = b4, a1 = b4, a2 = b4, a3 = b4;
    for (int jh = 0; jh < 2; ++jh) {
        if (jh == 1) {
            __syncthreads();
            for (int i = tid; i < 2048; i += 256)
                ((float4*)Wsh)[i] = ((const float4*)Wout)[2048 + i];
            __syncthreads();
        }
#pragma unroll 8
        for (int j = 0; j < 64; ++j) {
            int jj = (jh << 6) + j;
            float4 w = ((const float4*)(Wsh + j * Dc))[tcol];
            float e0 = Ash[(trow)      * Dc + jj];
            float e1 = Ash[(trow + 8)  * Dc + jj];
            float e2 = Ash[(trow + 16) * Dc + jj];
            float e3 = Ash[(trow + 24) * Dc + jj];
            a0.x = fmaf(e0, w.x, a0.x); a0.y = fmaf(e0, w.y, a0.y);
            a0.z = fmaf(e0, w.z, a0.z); a0.w = fmaf(e0, w.w, a0.w);
            a1.x = fmaf(e1, w.x, a1.x); a1.y = fmaf(e1, w.y, a1.y);
            a1.z = fmaf(e1, w.z, a1.z); a1.w = fmaf(e1, w.w, a1.w);
            a2.x = fmaf(e2, w.x, a2.x); a2.y = fmaf(e2, w.y, a2.y);
            a2.z = fmaf(e2, w.z, a2.z); a2.w = fmaf(e2, w.w, a2.w);
            a3.x = fmaf(e3, w.x, a3.x); a3.y = fmaf(e3, w.y, a3.y);
            a3.z = fmaf(e3, w.z, a3.z); a3.w = fmaf(e3, w.w, a3.w);
        }
    }
    ((float4*)(out + EMD_OFF + (size_t)(rowbase + trow)      * Dc))[tcol] = a0;
    ((float4*)(out + EMD_OFF + (size_t)(rowbase + trow + 8)  * Dc))[tcol] = a1;
    ((float4*)(out + EMD_OFF + (size_t)(rowbase + trow + 16) * Dc))[tcol] = a2;
    ((float4*)(out + EMD_OFF + (size_t)(rowbase + trow + 24) * Dc))[tcol] = a3;
}

// ---------------- launch (PDL-chained with early triggers) ------------------------
extern "C" void kernel_launch(void* const* d_in, const int* in_sizes, int n_in,
                              void* d_out, int out_size) {
    const float* qh     = (const float*)d_in[0];
    const float* qr     = (const float*)d_in[1];
    const float* qt     = (const float*)d_in[2];
    const float* rn     = (const float*)d_in[3];
    const float* tn     = (const float*)d_in[4];
    const float* tin    = (const float*)d_in[5];
    const float* hidden = (const float*)d_in[6];
    const float* temd   = (const float*)d_in[7];
    const int*   tidx   = (const int*)d_in[8];
    const int*   tnodes = (const int*)d_in[9];
    const float* Wq     = (const float*)d_in[10];
    const float* bq     = (const float*)d_in[11];
    const float* Wa     = (const float*)d_in[12];
    const float* ba     = (const float*)d_in[13];
    const float* Watt   = (const float*)d_in[14];
    const float* batt   = (const float*)d_in[15];
    const float* Wrule  = (const float*)d_in[16];
    const float* brule  = (const float*)d_in[17];
    const float* Wout   = (const float*)d_in[18];
    const float* bout   = (const float*)d_in[19];
    float* out = (float*)d_out;

    k_init<<<288, 256>>>(qh, qr, qt, Wq, bq, Wa, ba, Watt, batt);

    cudaLaunchAttribute attr[1];
    attr[0].id = cudaLaunchAttributeProgrammaticStreamSerialization;
    attr[0].val.programmaticStreamSerializationAllowed = 1;

    {
        cudaLaunchConfig_t cfg = {};
        cfg.gridDim = dim3(Ec / 16); cfg.blockDim = dim3(256);
        cfg.attrs = attr; cfg.numAttrs = 1;
        cudaLaunchKernelEx(&cfg, k_edge, rn, tn, tin, hidden, Wrule, brule, tidx);
    }
    {
        cudaLaunchConfig_t cfg = {};
        cfg.gridDim = dim3(Bc); cfg.blockDim = dim3(256);
        cfg.attrs = attr; cfg.numAttrs = 1;
        cudaLaunchKernelEx(&cfg, k_topk, tnodes, out);
    }
    {
        cudaLaunchConfig_t cfg = {};
        cfg.gridDim = dim3(BKc / 4); cfg.blockDim = dim3(256);
        cfg.attrs = attr; cfg.numAttrs = 1;
        cudaLaunchKernelEx(&cfg, k_gather, qh, rn, tin, hidden, temd, out);
    }
    {
        cudaLaunchConfig_t cfg = {};
        cfg.gridDim = dim3(BKc / 32); cfg.blockDim = dim3(256);
        cfg.attrs = attr; cfg.numAttrs = 1;
        cudaLaunchKernelEx(&cfg, k_out, Wout, bout, out);
    }
}

// round 15
// speedup vs baseline: 1.0403x; 1.0403x over previous
#include <cuda_runtime.h>
#include <math.h>

// Problem constants
#define Bc   32
#define Nc   4096
#define Dc   128
#define Kc   512
#define NPBc 2048
#define Mc   (Bc * NPBc)   // 65536
#define Ec   (Bc * Nc)     // 131072
#define TDc  384
#define MAXC 32
#define BKc  (Bc * Kc)     // 16384

// Output layout (flattened tuple, fp32)
#define EMD_OFF 32768
#define HID_OFF 2129920

typedef unsigned long long ull;

// ---------------- scratch (static device globals; no allocations) -------------
__device__ __align__(16) float  g_v[Bc * TDc];
__device__ float                g_sf[Bc];
__device__ float                g_att[Ec];
__device__ int                  g_cnt[Mc];
__device__ int                  g_list[Mc * MAXC];
__device__ double               g_agg[Mc];
__device__ int                  g_topk[BKc];
__device__ __align__(16) float  g_emd[(size_t)BKc * Dc];

// ================= K1: fused zero + per-batch precompute (coalesced, ILP) =======
__global__ void __launch_bounds__(256) k_init(
    const float* __restrict__ qh, const float* __restrict__ qr,
    const float* __restrict__ qt, const float* __restrict__ Wq,
    const float* __restrict__ bq, const float* __restrict__ Wa,
    const float* __restrict__ ba, const float* __restrict__ Watt,
    const float* __restrict__ batt) {
    cudaTriggerProgrammaticLaunchCompletion();
    if (blockIdx.x < 256) {
        int i = blockIdx.x * 256 + threadIdx.x;
        g_cnt[i] = 0;
        g_agg[i] = 0.0;
        return;
    }
    int b    = blockIdx.x - 256;
    int tid  = threadIdx.x;
    int t    = tid & 127;
    int half = tid >> 7;
    int lane = tid & 31;
    int warp = tid >> 5;
    __shared__ float xS[TDc];
    __shared__ float redq[2 * Dc];
    __shared__ __align__(16) float cS[Dc];
    __shared__ float red[Dc];

    if (tid < 128) { xS[tid] = qh[b * Dc + tid]; xS[256 + tid] = qt[b * Dc + tid]; }
    else           { xS[tid] = qr[b * Dc + (tid - 128)]; }
    __syncthreads();

    {
        int jb = half * 192;
        float a0 = 0.f, a1 = 0.f, a2 = 0.f, a3 = 0.f;
#pragma unroll 8
        for (int j = 0; j < 192; j += 4) {
            a0 = fmaf(xS[jb + j],     Wq[(size_t)(jb + j) * Dc + t],     a0);
            a1 = fmaf(xS[jb + j + 1], Wq[(size_t)(jb + j + 1) * Dc + t], a1);
            a2 = fmaf(xS[jb + j + 2], Wq[(size_t)(jb + j + 2) * Dc + t], a2);
            a3 = fmaf(xS[jb + j + 3], Wq[(size_t)(jb + j + 3) * Dc + t], a3);
        }
        redq[half * Dc + t] = (a0 + a1) + (a2 + a3);
    }
    __syncthreads();

    if (tid < 128) {
        float q  = bq[t] + redq[t] + redq[Dc + t];
        float w1 = Watt[t], w2 = Watt[Dc + t], w3 = Watt[2 * Dc + t];
        float c  = q * w1 - w2 + w3;
        cS[t]  = c;
        red[t] = q * (w2 + w3) + ba[t] * c;
    }
    __syncthreads();
    for (int off = 64; off > 0; off >>= 1) {
        if (tid < off) red[tid] += red[tid + off];
        __syncthreads();
    }
    if (tid == 0) g_sf[b] = red[0] + batt[0];

    float4 cl = ((const float4*)cS)[lane];
    int base = warp * 48;
    for (int jj = 0; jj < 48; jj += 4) {
        int j = base + jj;
        float4 w0 = ((const float4*)(Wa + (size_t)(j)     * Dc))[lane];
        float4 w1 = ((const float4*)(Wa + (size_t)(j + 1) * Dc))[lane];
        float4 w2 = ((const float4*)(Wa + (size_t)(j + 2) * Dc))[lane];
        float4 w3 = ((const float4*)(Wa + (size_t)(j + 3) * Dc))[lane];
        float d0 = w0.x * cl.x; d0 = fmaf(w0.y, cl.y, d0);
        d0 = fmaf(w0.z, cl.z, d0); d0 = fmaf(w0.w, cl.w, d0);
        float d1 = w1.x * cl.x; d1 = fmaf(w1.y, cl.y, d1);
        d1 = fmaf(w1.z, cl.z, d1); d1 = fmaf(w1.w, cl.w, d1);
        float d2 = w2.x * cl.x; d2 = fmaf(w2.y, cl.y, d2);
        d2 = fmaf(w2.z, cl.z, d2); d2 = fmaf(w2.w, cl.w, d2);
        float d3 = w3.x * cl.x; d3 = fmaf(w3.y, cl.y, d3);
        d3 = fmaf(w3.z, cl.z, d3); d3 = fmaf(w3.w, cl.w, d3);
#pragma unroll
        for (int off = 16; off > 0; off >>= 1) {
            d0 += __shfl_xor_sync(0xffffffffu, d0, off);
            d1 += __shfl_xor_sync(0xffffffffu, d1, off);
            d2 += __shfl_xor_sync(0xffffffffu, d2, off);
            d3 += __shfl_xor_sync(0xffffffffu, d3, off);
        }
        if (lane == 0) {
            g_v[b * TDc + j]     = d0;
            g_v[b * TDc + j + 1] = d1;
            g_v[b * TDc + j + 2] = d2;
            g_v[b * TDc + j + 3] = d3;
        }
    }
}

// ================= K2: per-edge att (2 edges/warp), PDL-overlapped ===============
// L2 residency shaping: rn/tn evict-first (__ldcs); tin+hidden (128MB ~ L2 size)
// stay normal so k_gather's random re-reads of them hit L2.
__global__ void __launch_bounds__(256) k_edge(
    const float* __restrict__ rn,  const float* __restrict__ tn,
    const float* __restrict__ tin, const float* __restrict__ hidden,
    const float* __restrict__ Wrule, const float* __restrict__ brule,
    const int* __restrict__ tail_index) {
    cudaTriggerProgrammaticLaunchCompletion();
    int w    = blockIdx.x * 8 + (threadIdx.x >> 5);
    int lane = threadIdx.x & 31;
    int e0   = w * 2, e1 = e0 + 1;
    int b    = e0 >> 12;

    const float4 r4a  = __ldcs((const float4*)(rn  + (size_t)e0 * Dc) + lane);
    const float4 r4b  = __ldcs((const float4*)(rn  + (size_t)e1 * Dc) + lane);
    const float4 t4a  = __ldcs((const float4*)(tn  + (size_t)e0 * Dc) + lane);
    const float4 t4b  = __ldcs((const float4*)(tn  + (size_t)e1 * Dc) + lane);
    const float4 ti4a = ((const float4*)(tin + (size_t)e0 * Dc))[lane];
    const float4 ti4b = ((const float4*)(tin + (size_t)e1 * Dc))[lane];
    const float4 h4a  = ((const float4*)(hidden + (size_t)e0 * Dc))[lane];
    const float4 h4b  = ((const float4*)(hidden + (size_t)e1 * Dc))[lane];
    float4 w4 = ((const float4*)Wrule)[lane];
    int   m0 = tail_index[e0];
    int   m1 = tail_index[e1];
    float br = brule[0];

    cudaGridDependencySynchronize();

    const float4* vp = (const float4*)(g_v + b * TDc);
    float4 vA = vp[lane], vB = vp[32 + lane], vC = vp[64 + lane];

    float s1a = r4a.x * vA.x;
    s1a = fmaf(r4a.y, vA.y, s1a);  s1a = fmaf(r4a.z, vA.z, s1a);  s1a = fmaf(r4a.w, vA.w, s1a);
    s1a = fmaf(t4a.x, vB.x, s1a);  s1a = fmaf(t4a.y, vB.y, s1a);
    s1a = fmaf(t4a.z, vB.z, s1a);  s1a = fmaf(t4a.w, vB.w, s1a);
    s1a = fmaf(ti4a.x, vC.x, s1a); s1a = fmaf(ti4a.y, vC.y, s1a);
    s1a = fmaf(ti4a.z, vC.z, s1a); s1a = fmaf(ti4a.w, vC.w, s1a);

    float s1b = r4b.x * vA.x;
    s1b = fmaf(r4b.y, vA.y, s1b);  s1b = fmaf(r4b.z, vA.z, s1b);  s1b = fmaf(r4b.w, vA.w, s1b);
    s1b = fmaf(t4b.x, vB.x, s1b);  s1b = fmaf(t4b.y, vB.y, s1b);
    s1b = fmaf(t4b.z, vB.z, s1b);  s1b = fmaf(t4b.w, vB.w, s1b);
    s1b = fmaf(ti4b.x, vC.x, s1b); s1b = fmaf(ti4b.y, vC.y, s1b);
    s1b = fmaf(ti4b.z, vC.z, s1b); s1b = fmaf(ti4b.w, vC.w, s1b);

    float s2a = h4a.x * w4.x;
    s2a = fmaf(h4a.y, w4.y, s2a);  s2a = fmaf(h4a.z, w4.z, s2a);  s2a = fmaf(h4a.w, w4.w, s2a);
    float s2b = h4b.x * w4.x;
    s2b = fmaf(h4b.y, w4.y, s2b);  s2b = fmaf(h4b.z, w4.z, s2b);  s2b = fmaf(h4b.w, w4.w, s2b);

#pragma unroll
    for (int off = 16; off > 0; off >>= 1) {
        s1a += __shfl_xor_sync(0xffffffffu, s1a, off);
        s1b += __shfl_xor_sync(0xffffffffu, s1b, off);
        s2a += __shfl_xor_sync(0xffffffffu, s2a, off);
        s2b += __shfl_xor_sync(0xffffffffu, s2b, off);
    }

    float sf = g_sf[b];
    if (lane == 0) {
        float att = 0.5f * (1.0f / (1.0f + expf(-(s1a + sf))) +
                            1.0f / (1.0f + expf(-(s2a + br))));
        g_att[e0] = att;
        atomicAdd(&g_agg[m0], (double)att);
        int pos = atomicAdd(&g_cnt[m0], 1);
        if (pos < MAXC) g_list[m0 * MAXC + pos] = e0;
    } else if (lane == 16) {
        float att = 0.5f * (1.0f / (1.0f + expf(-(s1b + sf))) +
                            1.0f / (1.0f + expf(-(s2b + br))));
        g_att[e1] = att;
        atomicAdd(&g_agg[m1], (double)att);
        int pos = atomicAdd(&g_cnt[m1], 1);
        if (pos < MAXC) g_list[m1 * MAXC + pos] = e1;
    }
}

// ================= K3: exact radix-select top-512 (1024 threads, proven) =========
__global__ void __launch_bounds__(1024) k_topk(const int* __restrict__ tail_nodes,
                                               float* __restrict__ out) {
    cudaTriggerProgrammaticLaunchCompletion();   // let k_gather pre-place
    int b    = blockIdx.x;
    int tid  = threadIdx.x;
    int lane = tid & 31;

    __shared__ unsigned int hist[256];
    __shared__ unsigned int sufS[258];
    __shared__ ull   sPrefix;
    __shared__ int   sRem;
    __shared__ int   sCnt;
    __shared__ ull   arr[Kc];

    cudaGridDependencySynchronize();   // wait for k_edge's g_agg

    int i0 = tid, i1 = tid + 1024;
    ull k0 = (__double_as_longlong(g_agg[b * NPBc + i0]) & 0xFFFFFFFFFFFF0000ull)
             | (ull)(2047 - i0);
    ull k1 = (__double_as_longlong(g_agg[b * NPBc + i1]) & 0xFFFFFFFFFFFF0000ull)
             | (ull)(2047 - i1);

    ull prefix = 0;
    int rem    = Kc;
    for (int d = 7; d >= 0; --d) {
        if (tid < 256) hist[tid] = 0;
        __syncthreads();
        int shHi = (d < 7) ? (8 * d + 8) : 0;
        bool m0 = (d == 7) || ((k0 >> shHi) == prefix);
        bool m1 = (d == 7) || ((k1 >> shHi) == prefix);
        if (m0) atomicAdd(&hist[(unsigned)(k0 >> (8 * d)) & 0xFF], 1u);
        if (m1) atomicAdd(&hist[(unsigned)(k1 >> (8 * d)) & 0xFF], 1u);
        __syncthreads();
        if (tid < 32) {
            unsigned v[8], suf[8];
            unsigned run = 0;
#pragma unroll
            for (int j = 7; j >= 0; --j) { v[j] = hist[lane * 8 + j]; run += v[j]; suf[j] = run; }
            unsigned tot = run, s = tot;
#pragma unroll
            for (int off = 1; off < 32; off <<= 1) {
                unsigned o = __shfl_down_sync(0xffffffffu, s, off);
                if (lane + off < 32) s += o;
            }
            unsigned excl = s - tot;
#pragma unroll
            for (int j = 0; j < 8; ++j) sufS[lane * 8 + j] = suf[j] + excl;
            if (lane == 0) sufS[256] = 0;
            __syncwarp();
#pragma unroll
            for (int j = 0; j < 8; ++j) {
                int t = lane * 8 + j;
                unsigned st = sufS[t], st1 = sufS[t + 1];
                if (st >= (unsigned)rem && st1 < (unsigned)rem) {
                    sPrefix = (prefix << 8) | (ull)(unsigned)t;
                    sRem    = rem - (int)st1;
                }
            }
        }
        __syncthreads();
        prefix = sPrefix;
        rem    = sRem;
        __syncthreads();
    }
    ull T = prefix;

    if (tid == 0) sCnt = 0;
    __syncthreads();
    if (k0 >= T) arr[atomicAdd(&sCnt, 1)] = k0;
    if (k1 >= T) arr[atomicAdd(&sCnt, 1)] = k1;
    __syncthreads();

    if (tid < Kc) {
        ull v = arr[tid];
#pragma unroll
        for (int size = 2; size <= 32; size <<= 1) {
#pragma unroll
            for (int stride = size >> 1; stride >= 1; stride >>= 1) {
                ull  vo  = __shfl_xor_sync(0xffffffffu, v, stride);
                bool low = (lane & stride) == 0;
                bool up  = ((tid & size) == 0);
                bool pm  = v > vo;
                if (pm != (up == low)) v = vo;
            }
        }
        arr[tid] = v;
    }
    __syncthreads();
    for (int size = 64; size <= Kc; size <<= 1) {
        for (int stride = size >> 1; stride >= 32; stride >>= 1) {
            if (tid < Kc) {
                int t = tid, l = t ^ stride;
                if (l > t) {
                    bool up = ((t & size) == 0);
                    ull v1 = arr[t], v2 = arr[l];
                    bool prec = v1 > v2;
                    if (up ? !prec : prec) { arr[t] = v2; arr[l] = v1; }
                }
            }
            __syncthreads();
        }
        if (tid < Kc) {
            ull v = arr[tid];
            bool up = ((tid & size) == 0);
#pragma unroll
            for (int stride = 16; stride >= 1; stride >>= 1) {
                ull  vo  = __shfl_xor_sync(0xffffffffu, v, stride);
                bool low = (lane & stride) == 0;
                bool pm  = v > vo;
                if (pm != (up == low)) v = vo;
            }
            arr[tid] = v;
        }
        __syncthreads();
    }

    if (tid < Kc) {
        int i = 2047 - (int)(arr[tid] & 0xFFFFull);
        int m = b * NPBc + i;
        g_topk[b * Kc + tid] = m;
        out[(size_t)(b * Kc + tid) * 2 + 0] = (float)tail_nodes[m * 3 + 1];
        out[(size_t)(b * Kc + tid) * 2 + 1] = (float)tail_nodes[m * 3 + 2];
    }
}

// ---- warp bitonic ascending sort of 32 unsigned (distinct; invalid=0xffffffff) --
__device__ __forceinline__ unsigned warp_sort_asc(unsigned v, int lane) {
#pragma unroll
    for (int size = 2; size <= 32; size <<= 1) {
#pragma unroll
        for (int stride = size >> 1; stride >= 1; stride >>= 1) {
            unsigned vo = __shfl_xor_sync(0xffffffffu, v, stride);
            bool low = (lane & stride) == 0;
            bool up  = ((lane & size) == 0);
            bool mineSmall = v < vo;
            if (mineSmall != (up == low)) v = vo;
        }
    }
    return v;
}

// ================= K4: gather — 1 row per warp-pair, PDL =========================
__global__ void __launch_bounds__(256, 6) k_gather(
    const float* __restrict__ qh, const float* __restrict__ rn,
    const float* __restrict__ tin, const float* __restrict__ hidden,
    const float* __restrict__ temd, float* __restrict__ out) {
    cudaTriggerProgrammaticLaunchCompletion();   // let k_out pre-place + preload W
    int warp = threadIdx.x >> 5;
    int row  = blockIdx.x * 4 + (warp >> 1);
    int role = warp & 1;
    int lane = threadIdx.x & 31;
    int b    = row >> 9;

    float4 qh4 = ((const float4*)(qh + (size_t)b * Dc))[lane];  // pre-sync

    cudaGridDependencySynchronize();   // wait for k_topk's g_topk

    int m = g_topk[row];
    int k = g_cnt[m];
    if (k > MAXC) k = MAXC;
    unsigned ev = (lane < k) ? (unsigned)g_list[m * MAXC + lane] : 0xffffffffu;
    unsigned sorted = warp_sort_asc(ev, lane);
    float attL = (lane < k) ? g_att[(int)sorted] : 0.f;

    if (role == 0) {
        float aggf = (float)g_agg[m];
        float4 acc = ((const float4*)(temd + (size_t)m * Dc))[lane];
        acc.x = fmaf(aggf, qh4.x, acc.x);
        acc.y = fmaf(aggf, qh4.y, acc.y);
        acc.z = fmaf(aggf, qh4.z, acc.z);
        acc.w = fmaf(aggf, qh4.w, acc.w);

        int r = 0;
        for (; r + 3 < k; r += 4) {
            int e0 = (int)__shfl_sync(0xffffffffu, sorted, r);
            int e1 = (int)__shfl_sync(0xffffffffu, sorted, r + 1);
            int e2 = (int)__shfl_sync(0xffffffffu, sorted, r + 2);
            int e3 = (int)__shfl_sync(0xffffffffu, sorted, r + 3);
            float a0 = __shfl_sync(0xffffffffu, attL, r);
            float a1 = __shfl_sync(0xffffffffu, attL, r + 1);
            float a2 = __shfl_sync(0xffffffffu, attL, r + 2);
            float a3 = __shfl_sync(0xffffffffu, attL, r + 3);
            float4 r40  = ((const float4*)(rn  + (size_t)e0 * Dc))[lane];
            float4 ti40 = ((const float4*)(tin + (size_t)e0 * Dc))[lane];
            float4 r41  = ((const float4*)(rn  + (size_t)e1 * Dc))[lane];
            float4 ti41 = ((const float4*)(tin + (size_t)e1 * Dc))[lane];
            float4 r42  = ((const float4*)(rn  + (size_t)e2 * Dc))[lane];
            float4 ti42 = ((const float4*)(tin + (size_t)e2 * Dc))[lane];
            float4 r43  = ((const float4*)(rn  + (size_t)e3 * Dc))[lane];
            float4 ti43 = ((const float4*)(tin + (size_t)e3 * Dc))[lane];
            acc.x += a0 * (r40.x + ti40.x) + a1 * (r41.x + ti41.x);
            acc.y += a0 * (r40.y + ti40.y) + a1 * (r41.y + ti41.y);
            acc.z += a0 * (r40.z + ti40.z) + a1 * (r41.z + ti41.z);
            acc.w += a0 * (r40.w + ti40.w) + a1 * (r41.w + ti41.w);
            acc.x += a2 * (r42.x + ti42.x) + a3 * (r43.x + ti43.x);
            acc.y += a2 * (r42.y + ti42.y) + a3 * (r43.y + ti43.y);
            acc.z += a2 * (r42.z + ti42.z) + a3 * (r43.z + ti43.z);
            acc.w += a2 * (r42.w + ti42.w) + a3 * (r43.w + ti43.w);
        }
        if (r + 1 < k) {
            int e0 = (int)__shfl_sync(0xffffffffu, sorted, r);
            int e1 = (int)__shfl_sync(0xffffffffu, sorted, r + 1);
            float a0 = __shfl_sync(0xffffffffu, attL, r);
            float a1 = __shfl_sync(0xffffffffu, attL, r + 1);
            float4 r40  = ((const float4*)(rn  + (size_t)e0 * Dc))[lane];
            float4 ti40 = ((const float4*)(tin + (size_t)e0 * Dc))[lane];
            float4 r41  = ((const float4*)(rn  + (size_t)e1 * Dc))[lane];
            float4 ti41 = ((const float4*)(tin + (size_t)e1 * Dc))[lane];
            acc.x += a0 * (r40.x + ti40.x) + a1 * (r41.x + ti41.x);
            acc.y += a0 * (r40.y + ti40.y) + a1 * (r41.y + ti41.y);
            acc.z += a0 * (r40.z + ti40.z) + a1 * (r41.z + ti41.z);
            acc.w += a0 * (r40.w + ti40.w) + a1 * (r41.w + ti41.w);
            r += 2;
        }
        if (r < k) {
            int e = (int)__shfl_sync(0xffffffffu, sorted, r);
            float a = __shfl_sync(0xffffffffu, attL, r);
            float4 r4  = ((const float4*)(rn  + (size_t)e * Dc))[lane];
            float4 ti4 = ((const float4*)(tin + (size_t)e * Dc))[lane];
            acc.x += a * (r4.x + ti4.x);
            acc.y += a * (r4.y + ti4.y);
            acc.z += a * (r4.z + ti4.z);
            acc.w += a * (r4.w + ti4.w);
        }
        ((float4*)(g_emd + (size_t)row * Dc))[lane] = acc;
    } else {
        float4 hac = make_float4(0.f, 0.f, 0.f, 0.f);
        int r = 0;
        for (; r + 3 < k; r += 4) {
            int e0 = (int)__shfl_sync(0xffffffffu, sorted, r);
            int e1 = (int)__shfl_sync(0xffffffffu, sorted, r + 1);
            int e2 = (int)__shfl_sync(0xffffffffu, sorted, r + 2);
            int e3 = (int)__shfl_sync(0xffffffffu, sorted, r + 3);
            float4 h0 = ((const float4*)(hidden + (size_t)e0 * Dc))[lane];
            float4 h1 = ((const float4*)(hidden + (size_t)e1 * Dc))[lane];
            float4 h2 = ((const float4*)(hidden + (size_t)e2 * Dc))[lane];
            float4 h3 = ((const float4*)(hidden + (size_t)e3 * Dc))[lane];
            hac.x += h0.x + h1.x; hac.y += h0.y + h1.y;
            hac.z += h0.z + h1.z; hac.w += h0.w + h1.w;
            hac.x += h2.x + h3.x; hac.y += h2.y + h3.y;
            hac.z += h2.z + h3.z; hac.w += h2.w + h3.w;
        }
        if (r + 1 < k) {
            int e0 = (int)__shfl_sync(0xffffffffu, sorted, r);
            int e1 = (int)__shfl_sync(0xffffffffu, sorted, r + 1);
            float4 h0 = ((const float4*)(hidden + (size_t)e0 * Dc))[lane];
            float4 h1 = ((const float4*)(hidden + (size_t)e1 * Dc))[lane];
            hac.x += h0.x + h1.x; hac.y += h0.y + h1.y;
            hac.z += h0.z + h1.z; hac.w += h0.w + h1.w;
            r += 2;
        }
        if (r < k) {
            int e = (int)__shfl_sync(0xffffffffu, sorted, r);
            float4 h0 = ((const float4*)(hidden + (size_t)e * Dc))[lane];
            hac.x += h0.x; hac.y += h0.y; hac.z += h0.z; hac.w += h0.w;
        }
        ((float4*)(out + HID_OFF + (size_t)row * Dc))[lane] = hac;
    }
}

// ================= K5: output matvec; W half0 preloaded pre-sync (PDL) ===========
__global__ void __launch_bounds__(256) k_out(const float* __restrict__ Wout,
                                             const float* __restrict__ bout,
                                             float* __restrict__ out) {
    __shared__ float Wsh[64 * Dc];   // 32KB: one half of W_out
    __shared__ float Ash[32 * Dc];   // 16KB: this block's 32 emd rows
    int tid  = threadIdx.x;
    int tcol = tid & 31;
    int trow = tid >> 5;
    int rowbase = blockIdx.x * 32;

    for (int i = tid; i < 2048; i += 256)
        ((float4*)Wsh)[i] = ((const float4*)Wout)[i];
    float4 b4 = ((const float4*)bout)[tcol];

    cudaGridDependencySynchronize();   // wait for k_gather's g_emd

    for (int i = tid; i < 1024; i += 256)
        ((float4*)Ash)[i] = ((const float4*)(g_emd + (size_t)rowbase * Dc))[i];
    __syncthreads();

    float4 a0 = b4, a1 = b4, a2 = b4, a3 = b4;
    for (int jh = 0; jh < 2; ++jh) {
        if (jh == 1) {
            __syncthreads();
            for (int i = tid; i < 2048; i += 256)
                ((float4*)Wsh)[i] = ((const float4*)Wout)[2048 + i];
            __syncthreads();
        }
#pragma unroll 8
        for (int j = 0; j < 64; ++j) {
            int jj = (jh << 6) + j;
            float4 w = ((const float4*)(Wsh + j * Dc))[tcol];
            float e0 = Ash[(trow)      * Dc + jj];
            float e1 = Ash[(trow + 8)  * Dc + jj];
            float e2 = Ash[(trow + 16) * Dc + jj];
            float e3 = Ash[(trow + 24) * Dc + jj];
            a0.x = fmaf(e0, w.x, a0.x); a0.y = fmaf(e0, w.y, a0.y);
            a0.z = fmaf(e0, w.z, a0.z); a0.w = fmaf(e0, w.w, a0.w);
            a1.x = fmaf(e1, w.x, a1.x); a1.y = fmaf(e1, w.y, a1.y);
            a1.z = fmaf(e1, w.z, a1.z); a1.w = fmaf(e1, w.w, a1.w);
            a2.x = fmaf(e2, w.x, a2.x); a2.y = fmaf(e2, w.y, a2.y);
            a2.z = fmaf(e2, w.z, a2.z); a2.w = fmaf(e2, w.w, a2.w);
            a3.x = fmaf(e3, w.x, a3.x); a3.y = fmaf(e3, w.y, a3.y);
            a3.z = fmaf(e3, w.z, a3.z); a3.w = fmaf(e3, w.w, a3.w);
        }
    }
    ((float4*)(out + EMD_OFF + (size_t)(rowbase + trow)      * Dc))[tcol] = a0;
    ((float4*)(out + EMD_OFF + (size_t)(rowbase + trow + 8)  * Dc))[tcol] = a1;
    ((float4*)(out + EMD_OFF + (size_t)(rowbase + trow + 16) * Dc))[tcol] = a2;
    ((float4*)(out + EMD_OFF + (size_t)(rowbase + trow + 24) * Dc))[tcol] = a3;
}

// ---------------- launch (PDL-chained with early triggers) ------------------------
extern "C" void kernel_launch(void* const* d_in, const int* in_sizes, int n_in,
                              void* d_out, int out_size) {
    const float* qh     = (const float*)d_in[0];
    const float* qr     = (const float*)d_in[1];
    const float* qt     = (const float*)d_in[2];
    const float* rn     = (const float*)d_in[3];
    const float* tn     = (const float*)d_in[4];
    const float* tin    = (const float*)d_in[5];
    const float* hidden = (const float*)d_in[6];
    const float* temd   = (const float*)d_in[7];
    const int*   tidx   = (const int*)d_in[8];
    const int*   tnodes = (const int*)d_in[9];
    const float* Wq     = (const float*)d_in[10];
    const float* bq     = (const float*)d_in[11];
    const float* Wa     = (const float*)d_in[12];
    const float* ba     = (const float*)d_in[13];
    const float* Watt   = (const float*)d_in[14];
    const float* batt   = (const float*)d_in[15];
    const float* Wrule  = (const float*)d_in[16];
    const float* brule  = (const float*)d_in[17];
    const float* Wout   = (const float*)d_in[18];
    const float* bout   = (const float*)d_in[19];
    float* out = (float*)d_out;

    k_init<<<288, 256>>>(qh, qr, qt, Wq, bq, Wa, ba, Watt, batt);

    cudaLaunchAttribute attr[1];
    attr[0].id = cudaLaunchAttributeProgrammaticStreamSerialization;
    attr[0].val.programmaticStreamSerializationAllowed = 1;

    {
        cudaLaunchConfig_t cfg = {};
        cfg.gridDim = dim3(Ec / 16); cfg.blockDim = dim3(256);
        cfg.attrs = attr; cfg.numAttrs = 1;
        cudaLaunchKernelEx(&cfg, k_edge, rn, tn, tin, hidden, Wrule, brule, tidx);
    }
    {
        cudaLaunchConfig_t cfg = {};
        cfg.gridDim = dim3(Bc); cfg.blockDim = dim3(1024);
        cfg.attrs = attr; cfg.numAttrs = 1;
        cudaLaunchKernelEx(&cfg, k_topk, tnodes, out);
    }
    {
        cudaLaunchConfig_t cfg = {};
        cfg.gridDim = dim3(BKc / 4); cfg.blockDim = dim3(256);
        cfg.attrs = attr; cfg.numAttrs = 1;
        cudaLaunchKernelEx(&cfg, k_gather, qh, rn, tin, hidden, temd, out);
    }
    {
        cudaLaunchConfig_t cfg = {};
        cfg.gridDim = dim3(BKc / 32); cfg.blockDim = dim3(256);
        cfg.attrs = attr; cfg.numAttrs = 1;
        cudaLaunchKernelEx(&cfg, k_out, Wout, bout, out);
    }
}